// round 3
// baseline (speedup 1.0000x reference)
#include <cuda_runtime.h>
#include <math_constants.h>

#define NB    1024
#define NF    1024
#define NK    (NF + 1)
#define ND    256              // dilation units == erosion units
#define NOUT  512
#define NBLK  128
#define NTHR  256
#define GSZ   (NBLK * NTHR)    // 32768 threads
#define W4    (NK * ND / 4)    // 65600 float4 per weight matrix

// Control block, reset each launch by one 20-byte cudaMemsetAsync.
//   bounds[0]= enc(max dil)  bounds[1]= ~enc(min dil)
//   bounds[2]= enc(max ero)  bounds[3]= ~enc(min ero)   (all atomicMax, init 0)
struct Ctrl { unsigned bounds[4]; unsigned done; };
__device__ Ctrl g_ctrl;

__device__ __forceinline__ unsigned enc_f(float f) {
    unsigned u = __float_as_uint(f);
    return (u & 0x80000000u) ? ~u : (u | 0x80000000u);
}
__device__ __forceinline__ float dec_f(unsigned u) {
    return (u & 0x80000000u) ? __uint_as_float(u & 0x7fffffffu)
                             : __uint_as_float(~u);
}

__device__ __forceinline__ float wmax(float v) {
    #pragma unroll
    for (int o = 16; o > 0; o >>= 1) v = fmaxf(v, __shfl_xor_sync(0xffffffffu, v, o));
    return v;
}
__device__ __forceinline__ float wmin(float v) {
    #pragma unroll
    for (int o = 16; o > 0; o >>= 1) v = fminf(v, __shfl_xor_sync(0xffffffffu, v, o));
    return v;
}

__device__ __forceinline__ float4 max4(float4 a, float vv, float4 w) {
    a.x = fmaxf(a.x, vv + w.x); a.y = fmaxf(a.y, vv + w.y);
    a.z = fmaxf(a.z, vv + w.z); a.w = fmaxf(a.w, vv + w.w);
    return a;
}
__device__ __forceinline__ float4 min4(float4 a, float vv, float4 w) {
    a.x = fminf(a.x, vv - w.x); a.y = fminf(a.y, vv - w.y);
    a.z = fminf(a.z, vv - w.z); a.w = fminf(a.w, vv - w.w);
    return a;
}

__global__ __launch_bounds__(NTHR, 1) void dilate_erode_fused(
    const float* __restrict__ x,
    const float* __restrict__ dil,
    const float* __restrict__ ero,
    float* __restrict__ out)
{
    const int tid  = threadIdx.x;
    const int blk  = blockIdx.x;
    const int gtid = blk * NTHR + tid;
    const int lane = tid & 31;
    const int wrp  = tid >> 5;
    const int b    = blk * 8 + wrp;         // this warp's batch row

    const float4* __restrict__ x4   = (const float4*)x;
    const float4* __restrict__ dil4 = (const float4*)dil;
    const float4* __restrict__ ero4 = (const float4*)ero;
    float4* __restrict__ out4 = (float4*)out;

    // ---- issue x-row loads first: latency hides behind phase A ----
    float4 f[8];
    #pragma unroll
    for (int q = 0; q < 8; q++)
        f[q] = x4[b * 256 + q * 32 + lane];   // thread holds k = q*128 + lane*4 + c

    // =================== PHASE A: global weight spreads ===================
    {
        float dmx = -CUDART_INF_F, dmn = CUDART_INF_F;
        float emx = -CUDART_INF_F, emn = CUDART_INF_F;

        float4 d0 = dil4[gtid],        d1 = dil4[gtid + GSZ];
        float4 e0 = ero4[gtid],        e1 = ero4[gtid + GSZ];
        dmx = fmaxf(fmaxf(fmaxf(d0.x,d0.y),fmaxf(d0.z,d0.w)),
                    fmaxf(fmaxf(d1.x,d1.y),fmaxf(d1.z,d1.w)));
        dmn = fminf(fminf(fminf(d0.x,d0.y),fminf(d0.z,d0.w)),
                    fminf(fminf(d1.x,d1.y),fminf(d1.z,d1.w)));
        emx = fmaxf(fmaxf(fmaxf(e0.x,e0.y),fmaxf(e0.z,e0.w)),
                    fmaxf(fmaxf(e1.x,e1.y),fmaxf(e1.z,e1.w)));
        emn = fminf(fminf(fminf(e0.x,e0.y),fminf(e0.z,e0.w)),
                    fminf(fminf(e1.x,e1.y),fminf(e1.z,e1.w)));
        if (gtid < W4 - 2 * GSZ) {            // 64-float4 tail
            float4 d2 = dil4[gtid + 2 * GSZ];
            float4 e2 = ero4[gtid + 2 * GSZ];
            dmx = fmaxf(dmx, fmaxf(fmaxf(d2.x,d2.y),fmaxf(d2.z,d2.w)));
            dmn = fminf(dmn, fminf(fminf(d2.x,d2.y),fminf(d2.z,d2.w)));
            emx = fmaxf(emx, fmaxf(fmaxf(e2.x,e2.y),fmaxf(e2.z,e2.w)));
            emn = fminf(emn, fminf(fminf(e2.x,e2.y),fminf(e2.z,e2.w)));
        }

        __shared__ float s[4][8];
        dmx = wmax(dmx); dmn = wmin(dmn); emx = wmax(emx); emn = wmin(emn);
        if (lane == 0) { s[0][wrp]=dmx; s[1][wrp]=dmn; s[2][wrp]=emx; s[3][wrp]=emn; }
        __syncthreads();
        if (wrp == 0) {
            dmx = (lane<8)? s[0][lane] : -CUDART_INF_F;  dmx = wmax(dmx);
            dmn = (lane<8)? s[1][lane] :  CUDART_INF_F;  dmn = wmin(dmn);
            emx = (lane<8)? s[2][lane] : -CUDART_INF_F;  emx = wmax(emx);
            emn = (lane<8)? s[3][lane] :  CUDART_INF_F;  emn = wmin(emn);
            if (lane == 0) {
                atomicMax(&g_ctrl.bounds[0],  enc_f(dmx));
                atomicMax(&g_ctrl.bounds[1], ~enc_f(dmn));
                atomicMax(&g_ctrl.bounds[2],  enc_f(emx));
                atomicMax(&g_ctrl.bounds[3], ~enc_f(emn));
                __threadfence();
                atomicAdd(&g_ctrl.done, 1u);
            }
        }
    }

    // ---- software grid barrier (all 128 blocks resident by launch_bounds) ----
    if (tid == 0) {
        volatile unsigned* dp = &g_ctrl.done;
        while (*dp < NBLK) { __nanosleep(40); }
        __threadfence();
    }
    __syncthreads();

    volatile unsigned* vb = g_ctrl.bounds;
    const float spreadD = dec_f(vb[0]) - dec_f(~vb[1]);   // >= 0
    const float spreadE = dec_f(vb[2]) - dec_f(~vb[3]);   // >= 0

    // =================== PHASE B: warp-per-row tropical matmul ===================
    // per-float4 group extrema (used both for row reduce and candidate ballots)
    float gmx[8], gmn[8];
    float vmx = 0.0f, vmn = 0.0f;   // bias feature value 0 folded in
    #pragma unroll
    for (int q = 0; q < 8; q++) {
        gmx[q] = fmaxf(fmaxf(f[q].x, f[q].y), fmaxf(f[q].z, f[q].w));
        gmn[q] = fminf(fminf(f[q].x, f[q].y), fminf(f[q].z, f[q].w));
        vmx = fmaxf(vmx, gmx[q]);
        vmn = fminf(vmn, gmn[q]);
    }
    const float xmax = wmax(vmx);
    const float xmin = wmin(vmn);

    const float thD = xmax - spreadD;   // inclusive: every possible argmax survives
    const float thE = xmin + spreadE;   // inclusive: every possible argmin survives

    float4 dA0, dA1, eA0, eA1;
    dA0.x=dA0.y=dA0.z=dA0.w = -CUDART_INF_F;  dA1 = dA0;
    eA0.x=eA0.y=eA0.z=eA0.w =  CUDART_INF_F;  eA1 = eA0;

    // candidate scan: ballot on group maxima, then broadcast the 4 components
    #pragma unroll
    for (int q = 0; q < 8; q++) {
        unsigned mD = __ballot_sync(0xffffffffu, gmx[q] >= thD);
        while (mD) {
            int L = __ffs(mD) - 1;  mD &= mD - 1;
            float v0 = __shfl_sync(0xffffffffu, f[q].x, L);
            float v1 = __shfl_sync(0xffffffffu, f[q].y, L);
            float v2 = __shfl_sync(0xffffffffu, f[q].z, L);
            float v3 = __shfl_sync(0xffffffffu, f[q].w, L);
            int kb = q * 128 + L * 4;
            if (v0 >= thD) { dA0 = max4(dA0, v0, dil4[(kb  )*64 + 2*lane]); dA1 = max4(dA1, v0, dil4[(kb  )*64 + 2*lane+1]); }
            if (v1 >= thD) { dA0 = max4(dA0, v1, dil4[(kb+1)*64 + 2*lane]); dA1 = max4(dA1, v1, dil4[(kb+1)*64 + 2*lane+1]); }
            if (v2 >= thD) { dA0 = max4(dA0, v2, dil4[(kb+2)*64 + 2*lane]); dA1 = max4(dA1, v2, dil4[(kb+2)*64 + 2*lane+1]); }
            if (v3 >= thD) { dA0 = max4(dA0, v3, dil4[(kb+3)*64 + 2*lane]); dA1 = max4(dA1, v3, dil4[(kb+3)*64 + 2*lane+1]); }
        }
        unsigned mE = __ballot_sync(0xffffffffu, gmn[q] <= thE);
        while (mE) {
            int L = __ffs(mE) - 1;  mE &= mE - 1;
            float v0 = __shfl_sync(0xffffffffu, f[q].x, L);
            float v1 = __shfl_sync(0xffffffffu, f[q].y, L);
            float v2 = __shfl_sync(0xffffffffu, f[q].z, L);
            float v3 = __shfl_sync(0xffffffffu, f[q].w, L);
            int kb = q * 128 + L * 4;
            if (v0 <= thE) { eA0 = min4(eA0, v0, ero4[(kb  )*64 + 2*lane]); eA1 = min4(eA1, v0, ero4[(kb  )*64 + 2*lane+1]); }
            if (v1 <= thE) { eA0 = min4(eA0, v1, ero4[(kb+1)*64 + 2*lane]); eA1 = min4(eA1, v1, ero4[(kb+1)*64 + 2*lane+1]); }
            if (v2 <= thE) { eA0 = min4(eA0, v2, ero4[(kb+2)*64 + 2*lane]); eA1 = min4(eA1, v2, ero4[(kb+2)*64 + 2*lane+1]); }
            if (v3 <= thE) { eA0 = min4(eA0, v3, ero4[(kb+3)*64 + 2*lane]); eA1 = min4(eA1, v3, ero4[(kb+3)*64 + 2*lane+1]); }
        }
    }
    // bias feature k = NF, value 0 (uniform across warp)
    if (0.0f >= thD) { dA0 = max4(dA0, 0.0f, dil4[NF*64 + 2*lane]); dA1 = max4(dA1, 0.0f, dil4[NF*64 + 2*lane+1]); }
    if (0.0f <= thE) { eA0 = min4(eA0, 0.0f, ero4[NF*64 + 2*lane]); eA1 = min4(eA1, 0.0f, ero4[NF*64 + 2*lane+1]); }

    // store: eroded cols [0,256), dilated cols [256,512); thread owns j = 8*lane..8*lane+7
    out4[b * 128 +      2 * lane    ] = eA0;
    out4[b * 128 +      2 * lane + 1] = eA1;
    out4[b * 128 + 64 + 2 * lane    ] = dA0;
    out4[b * 128 + 64 + 2 * lane + 1] = dA1;
}

extern "C" void kernel_launch(void* const* d_in, const int* in_sizes, int n_in,
                              void* d_out, int out_size)
{
    (void)in_sizes; (void)n_in; (void)out_size;
    const float* x   = (const float*)d_in[0];
    const float* dil = (const float*)d_in[1];
    const float* ero = (const float*)d_in[2];
    float* out = (float*)d_out;

    void* ctrl_ptr = nullptr;
    cudaGetSymbolAddress(&ctrl_ptr, g_ctrl);
    cudaMemsetAsync(ctrl_ptr, 0, sizeof(Ctrl), 0);

    dilate_erode_fused<<<NBLK, NTHR>>>(x, dil, ero, out);
}